// round 7
// baseline (speedup 1.0000x reference)
#include <cuda_runtime.h>
#include <cuda_bf16.h>
#include <cstddef>
#include <cstdint>

// Problem constants
#define SS 2048
#define BB 64
#define DD 128
#define HH 128
#define GG 512   // 4*H

// 256 MB scratch for precomputed input gates: pre[t][b][512] = x@W_ih^T + b
__device__ float g_pre[(size_t)SS * BB * GG];

typedef unsigned long long ull;

// Packed fp32x2 ops (sm_100+)
#define FMA_F32X2(d, a, b, c) \
    asm("fma.rn.f32x2 %0, %1, %2, %3;" : "=l"(d) : "l"(a), "l"(b), "l"(c))
#define ADD_F32X2(d, a, b) \
    asm("add.rn.f32x2 %0, %1, %2;" : "=l"(d) : "l"(a), "l"(b))
#define PACK_DUP(out, f) \
    asm("mov.b64 %0, {%1, %1};" : "=l"(out) : "r"(__float_as_uint(f)))
#define UNPACK2(lo, hi, in) \
    asm("mov.b64 {%0, %1}, %2;" : "=f"(lo), "=f"(hi) : "l"(in))

// ---------------------------------------------------------------------------
// Kernel P: pre = X @ W_ih^T + bias (f32x2 version, passing since R3)
// ---------------------------------------------------------------------------
#define PSTRIDE 132
__global__ void __launch_bounds__(256) pre_gemm_kernel(
    const float* __restrict__ X,
    const float* __restrict__ Wih,
    const float* __restrict__ bias)
{
    extern __shared__ float sm[];
    float* Xs = sm;                       // [128][PSTRIDE]
    float* Ws = sm + 128 * PSTRIDE;       // [128][PSTRIDE]

    const int tid = threadIdx.x;
    const int row0 = blockIdx.x * 128;
    const int col0 = blockIdx.y * 128;

    #pragma unroll
    for (int it = 0; it < 64; it++) {
        int idx = it * 256 + tid;
        int i = idx >> 7;
        int k = idx & 127;
        Xs[k * PSTRIDE + i] = X[(size_t)(row0 + i) * DD + k];
    }
    #pragma unroll
    for (int it = 0; it < 64; it++) {
        int idx = it * 256 + tid;
        int j = idx >> 7;
        int k = idx & 127;
        Ws[k * PSTRIDE + j] = Wih[(size_t)(col0 + j) * DD + k];
    }
    __syncthreads();

    const int tx = tid & 15;
    const int ty = tid >> 4;

    ull acc2[8][4];
    #pragma unroll
    for (int i = 0; i < 8; i++)
        #pragma unroll
        for (int j = 0; j < 4; j++) acc2[i][j] = 0ULL;

    #pragma unroll 4
    for (int k = 0; k < 128; k++) {
        float4 a0 = *(const float4*)&Xs[k * PSTRIDE + ty * 8];
        float4 a1 = *(const float4*)&Xs[k * PSTRIDE + ty * 8 + 4];
        ulonglong2 b0 = *(const ulonglong2*)&Ws[k * PSTRIDE + tx * 8];
        ulonglong2 b1 = *(const ulonglong2*)&Ws[k * PSTRIDE + tx * 8 + 4];
        float av[8] = {a0.x, a0.y, a0.z, a0.w, a1.x, a1.y, a1.z, a1.w};
        ull bp[4] = {b0.x, b0.y, b1.x, b1.y};
        #pragma unroll
        for (int i = 0; i < 8; i++) {
            ull aa;
            PACK_DUP(aa, av[i]);
            #pragma unroll
            for (int j = 0; j < 4; j++)
                FMA_F32X2(acc2[i][j], aa, bp[j], acc2[i][j]);
        }
    }

    const int gcol = col0 + tx * 8;
    float bv8[8];
    #pragma unroll
    for (int j = 0; j < 8; j++) bv8[j] = bias[gcol + j];

    #pragma unroll
    for (int i = 0; i < 8; i++) {
        size_t r = (size_t)(row0 + ty * 8 + i);
        float* dst = g_pre + r * GG + gcol;
        float res[8];
        #pragma unroll
        for (int j = 0; j < 4; j++) {
            float lo, hi;
            UNPACK2(lo, hi, acc2[i][j]);
            res[2 * j]     = lo + bv8[2 * j];
            res[2 * j + 1] = hi + bv8[2 * j + 1];
        }
        *(float4*)&dst[0] = make_float4(res[0], res[1], res[2], res[3]);
        *(float4*)&dst[4] = make_float4(res[4], res[5], res[6], res[7]);
    }
}

// ---------------------------------------------------------------------------
// Cluster helpers
// ---------------------------------------------------------------------------
__device__ __forceinline__ uint32_t smem_u32(const void* p) {
    uint32_t a;
    asm("{ .reg .u64 t; cvta.to.shared.u64 t, %1; cvt.u32.u64 %0, t; }"
        : "=r"(a) : "l"(p));
    return a;
}
__device__ __forceinline__ uint32_t my_ctarank() {
    uint32_t r;
    asm("mov.u32 %0, %%cluster_ctarank;" : "=r"(r));
    return r;
}
__device__ __forceinline__ uint32_t mapa_u32(uint32_t local, uint32_t rank) {
    uint32_t r;
    asm("mapa.shared::cluster.u32 %0, %1, %2;" : "=r"(r) : "r"(local), "r"(rank));
    return r;
}
__device__ __forceinline__ void mbar_init(uint32_t addr, uint32_t count) {
    asm volatile("mbarrier.init.shared.b64 [%0], %1;"
                 :: "r"(addr), "r"(count) : "memory");
}
// Async store with HW transaction tracking (data + signal, no fences).
__device__ __forceinline__ void st_async_f32(uint32_t dst, float v, uint32_t mbar) {
    asm volatile(
        "st.async.shared::cluster.mbarrier::complete_tx::bytes.b32 [%0], %1, [%2];"
        :: "r"(dst), "r"(__float_as_uint(v)), "r"(mbar) : "memory");
}
__device__ __forceinline__ void mbar_expect_tx(uint32_t mbar, uint32_t bytes) {
    asm volatile("mbarrier.arrive.expect_tx.shared.b64 _, [%0], %1;"
                 :: "r"(mbar), "r"(bytes) : "memory");
}
__device__ __forceinline__ void mbar_wait(uint32_t mbar, uint32_t parity) {
    asm volatile(
        "{\n\t"
        ".reg .pred P;\n"
        "WL_%=:\n\t"
        "mbarrier.try_wait.parity.acquire.cta.shared::cta.b64 P, [%0], %1, 0x989680;\n\t"
        "@P bra WD_%=;\n\t"
        "bra WL_%=;\n"
        "WD_%=:\n\t"
        "}"
        :: "r"(mbar), "r"(parity) : "memory");
}
__device__ __forceinline__ void cluster_sync_hw() {
    asm volatile("barrier.cluster.arrive.aligned;" ::: "memory");
    asm volatile("barrier.cluster.wait.aligned;" ::: "memory");
}

__device__ __forceinline__ float fast_tanh(float x) {
    return 1.0f - __fdividef(2.0f, __expf(2.0f * x) + 1.0f);
}

// ---------------------------------------------------------------------------
// Kernel R: reverse scan, one 2-CTA CLUSTER per TWO batch elements.
// rank0 owns gate rows 0:256 (i,f); rank1 owns 256:512 (g,o). 256 thr/CTA.
// Each thread owns ONE gate row (weights register-resident, batch-invariant)
// and processes TWO independent batches per step — batch A's DSMEM flight
// overlaps batch B's compute, hiding the serial exchange latency.
// One ping-pong mbarrier per parity counts both batches (expect 4096 B).
// ---------------------------------------------------------------------------
__global__ void __launch_bounds__(256, 1) __cluster_dims__(2, 1, 1)
lstm_rev_cluster_kernel(
    const float* __restrict__ timeArr,   // [S*B]
    const float* __restrict__ Whh,       // [512,128]
    const float* __restrict__ w_t,       // [128]
    const float* __restrict__ b_t,       // [128]
    float* __restrict__ out)             // outputs ++ h ++ c
{
    __shared__ __align__(16) float hbuf[2][2][128];   // [parity][bat][k]
    __shared__ float act_all[2][2][512];              // [parity][bat][grow]
    __shared__ ull   mbars[2];

    const int tid   = threadIdx.x;
    const uint32_t rank  = my_ctarank();
    const uint32_t prank = 1u - rank;
    const int cl  = blockIdx.x >> 1;
    const int bA  = 2 * cl;              // two batches per cluster
    const int grow  = (int)rank * 256 + tid;   // global gate row

    // ALL weights register-resident: 64 ull = 128 floats (shared by A & B)
    ull wR[64];
    {
        const ull* wp = (const ull*)(Whh + (size_t)grow * HH);
        #pragma unroll
        for (int c = 0; c < 64; c++) wR[c] = wp[c];
    }

    // Cluster-space addresses
    const uint32_t mb0_l = smem_u32(&mbars[0]);
    const uint32_t mb1_l = smem_u32(&mbars[1]);
    uint32_t dstA_own[2], dstA_peer[2], mb_own[2], mb_peer[2];
    #pragma unroll
    for (int m = 0; m < 2; m++) {
        uint32_t a = smem_u32(&act_all[m][0][grow]);
        dstA_own[m]  = mapa_u32(a, rank);
        dstA_peer[m] = mapa_u32(a, prank);
        uint32_t mb = (m == 0) ? mb0_l : mb1_l;
        mb_own[m]   = mapa_u32(mb, rank);
        mb_peer[m]  = mapa_u32(mb, prank);
    }
    // batch B act slots are at constant +2048 B from batch A's (same buffer)

    if (tid == 0) {
        mbar_init(mb0_l, 1);
        mbar_init(mb1_l, 1);
        mbar_expect_tx(mb0_l, 4096);   // 2 batches x 512 floats
        mbar_expect_tx(mb1_l, 4096);
    }
    if (tid < 128) { hbuf[0][0][tid] = 0.0f; hbuf[0][1][tid] = 0.0f; }

    const float wt = w_t[tid & 127];
    const float bt = b_t[tid & 127];
    float cregA = 0.0f, hlastA = 0.0f;
    float cregB = 0.0f, hlastB = 0.0f;

    __syncthreads();
    cluster_sync_hw();   // mbars init+armed visible cluster-wide

    const float* preP = g_pre + (size_t)bA * GG + grow;   // batch B = +GG
    float preA_nx = preP[(size_t)(SS - 1) * BB * GG];
    float preB_nx = preP[(size_t)(SS - 1) * BB * GG + GG];
    float tvA_nx  = timeArr[(size_t)(SS - 1) * BB + bA];
    float tvB_nx  = timeArr[(size_t)(SS - 1) * BB + bA + 1];

    const bool  is_g     = (rank == 1) && (tid < 128);
    const float gate_mul = is_g ? 2.0f : 1.0f;    // tanh = 2*sigmoid(2x)-1

    for (int s = 0; s < SS; s++) {
        const int t   = SS - 1 - s;
        const int cur = s & 1;
        const int m   = s & 1;
        const uint32_t par = (uint32_t)((s >> 1) & 1);

        const float preA = preA_nx, preB = preB_nx;
        const float tvA  = tvA_nx,  tvB  = tvB_nx;
        if (t > 0) {
            size_t o = (size_t)(t - 1) * BB * GG;
            preA_nx = preP[o];
            preB_nx = preP[o + GG];
            tvA_nx  = timeArr[(size_t)(t - 1) * BB + bA];
            tvB_nx  = timeArr[(size_t)(t - 1) * BB + bA + 1];
        }

        // ---- batch A dot + act + send ----
        {
            const ulonglong2* h2 = (const ulonglong2*)&hbuf[cur][0][0];
            ull ac[8];
            #pragma unroll
            for (int i = 0; i < 8; i++) ac[i] = 0ULL;
            #pragma unroll
            for (int i = 0; i < 8; i++) {
                ulonglong2 hva = h2[4 * i],     hvb = h2[4 * i + 1];
                ulonglong2 hvc = h2[4 * i + 2], hvd = h2[4 * i + 3];
                FMA_F32X2(ac[0], wR[8 * i],     hva.x, ac[0]);
                FMA_F32X2(ac[1], wR[8 * i + 1], hva.y, ac[1]);
                FMA_F32X2(ac[2], wR[8 * i + 2], hvb.x, ac[2]);
                FMA_F32X2(ac[3], wR[8 * i + 3], hvb.y, ac[3]);
                FMA_F32X2(ac[4], wR[8 * i + 4], hvc.x, ac[4]);
                FMA_F32X2(ac[5], wR[8 * i + 5], hvc.y, ac[5]);
                FMA_F32X2(ac[6], wR[8 * i + 6], hvd.x, ac[6]);
                FMA_F32X2(ac[7], wR[8 * i + 7], hvd.y, ac[7]);
            }
            ADD_F32X2(ac[0], ac[0], ac[1]);
            ADD_F32X2(ac[2], ac[2], ac[3]);
            ADD_F32X2(ac[4], ac[4], ac[5]);
            ADD_F32X2(ac[6], ac[6], ac[7]);
            ADD_F32X2(ac[0], ac[0], ac[2]);
            ADD_F32X2(ac[4], ac[4], ac[6]);
            ADD_F32X2(ac[0], ac[0], ac[4]);
            float lo, hi;
            UNPACK2(lo, hi, ac[0]);
            float gsum = preA + (lo + hi);
            float sg = __fdividef(1.0f, 1.0f + __expf(-gate_mul * gsum));
            float a  = is_g ? (2.0f * sg - 1.0f) : sg;
            st_async_f32(dstA_own[m],  a, mb_own[m]);
            st_async_f32(dstA_peer[m], a, mb_peer[m]);
        }

        // ---- batch B dot + act + send (overlaps A's DSMEM flight) ----
        {
            const ulonglong2* h2 = (const ulonglong2*)&hbuf[cur][1][0];
            ull ac[8];
            #pragma unroll
            for (int i = 0; i < 8; i++) ac[i] = 0ULL;
            #pragma unroll
            for (int i = 0; i < 8; i++) {
                ulonglong2 hva = h2[4 * i],     hvb = h2[4 * i + 1];
                ulonglong2 hvc = h2[4 * i + 2], hvd = h2[4 * i + 3];
                FMA_F32X2(ac[0], wR[8 * i],     hva.x, ac[0]);
                FMA_F32X2(ac[1], wR[8 * i + 1], hva.y, ac[1]);
                FMA_F32X2(ac[2], wR[8 * i + 2], hvb.x, ac[2]);
                FMA_F32X2(ac[3], wR[8 * i + 3], hvb.y, ac[3]);
                FMA_F32X2(ac[4], wR[8 * i + 4], hvc.x, ac[4]);
                FMA_F32X2(ac[5], wR[8 * i + 5], hvc.y, ac[5]);
                FMA_F32X2(ac[6], wR[8 * i + 6], hvd.x, ac[6]);
                FMA_F32X2(ac[7], wR[8 * i + 7], hvd.y, ac[7]);
            }
            ADD_F32X2(ac[0], ac[0], ac[1]);
            ADD_F32X2(ac[2], ac[2], ac[3]);
            ADD_F32X2(ac[4], ac[4], ac[5]);
            ADD_F32X2(ac[6], ac[6], ac[7]);
            ADD_F32X2(ac[0], ac[0], ac[2]);
            ADD_F32X2(ac[4], ac[4], ac[6]);
            ADD_F32X2(ac[0], ac[0], ac[4]);
            float lo, hi;
            UNPACK2(lo, hi, ac[0]);
            float gsum = preB + (lo + hi);
            float sg = __fdividef(1.0f, 1.0f + __expf(-gate_mul * gsum));
            float a  = is_g ? (2.0f * sg - 1.0f) : sg;
            st_async_f32(dstA_own[m]  + 2048, a, mb_own[m]);   // +2048B = bat 1
            st_async_f32(dstA_peer[m] + 2048, a, mb_peer[m]);
        }

        // single wait covers both batches, local + remote
        mbar_wait(m ? mb1_l : mb0_l, par);
        if (tid == 0)
            mbar_expect_tx(m ? mb1_l : mb0_l, 4096);  // re-arm for s+2

        if (tid < 128) {
            {   // batch A combine
                const float* A = &act_all[m][0][0];
                float iv = A[tid], fv = A[128 + tid];
                float gv = A[256 + tid], ov = A[384 + tid];
                float dec = __expf(-fmaxf(tvA * wt + bt, 0.0f));
                cregA = fv * cregA * dec + iv * gv;
                float hv = ov * fast_tanh(cregA);
                hlastA = hv;
                hbuf[cur ^ 1][0][tid] = hv;
                if (rank == 0)
                    out[(size_t)t * (BB * HH) + (size_t)bA * HH + tid] = hv;
            }
            {   // batch B combine
                const float* A = &act_all[m][1][0];
                float iv = A[tid], fv = A[128 + tid];
                float gv = A[256 + tid], ov = A[384 + tid];
                float dec = __expf(-fmaxf(tvB * wt + bt, 0.0f));
                cregB = fv * cregB * dec + iv * gv;
                float hv = ov * fast_tanh(cregB);
                hlastB = hv;
                hbuf[cur ^ 1][1][tid] = hv;
                if (rank == 0)
                    out[(size_t)t * (BB * HH) + (size_t)(bA + 1) * HH + tid] = hv;
            }
        }
        __syncthreads();   // h published; also orders re-arm before s+1 sends
    }

    // final state: h then c after the outputs block (rank0 only)
    if (rank == 0 && tid < 128) {
        size_t base = (size_t)SS * BB * HH;
        out[base + (size_t)bA * HH + tid] = hlastA;
        out[base + (size_t)(bA + 1) * HH + tid] = hlastB;
        out[base + (size_t)BB * HH + (size_t)bA * HH + tid] = cregA;
        out[base + (size_t)BB * HH + (size_t)(bA + 1) * HH + tid] = cregB;
    }

    cluster_sync_hw();   // no early exit while peer ops in flight
}

// ---------------------------------------------------------------------------
// Launch
// ---------------------------------------------------------------------------
extern "C" void kernel_launch(void* const* d_in, const int* in_sizes, int n_in,
                              void* d_out, int out_size)
{
    const float* X    = (const float*)d_in[0];  // input  (S,B,D)
    const float* Tm   = (const float*)d_in[1];  // time   (S,B,1)
    const float* Wih  = (const float*)d_in[2];  // (4H, D)
    const float* Whh  = (const float*)d_in[3];  // (4H, H)
    const float* bias = (const float*)d_in[4];  // (4H,)
    const float* wt   = (const float*)d_in[5];  // (H,)
    const float* bt   = (const float*)d_in[6];  // (H,)
    float* out = (float*)d_out;

    const int smemP = 2 * 128 * PSTRIDE * (int)sizeof(float);  // 135168 B
    cudaFuncSetAttribute(pre_gemm_kernel,
                         cudaFuncAttributeMaxDynamicSharedMemorySize, smemP);

    dim3 gridP((SS * BB) / 128, GG / 128);
    pre_gemm_kernel<<<gridP, 256, smemP>>>(X, Wih, bias);

    // 32 clusters of 2 CTAs (grid 64), 256 threads each, 2 batches/cluster
    lstm_rev_cluster_kernel<<<BB, 256>>>(Tm, Whh, wt, bt, out);
}

// round 8
// speedup vs baseline: 1.5683x; 1.5683x over previous
#include <cuda_runtime.h>
#include <cuda_bf16.h>
#include <cstddef>
#include <cstdint>

// Problem constants
#define SS 2048
#define BB 64
#define DD 128
#define HH 128
#define GG 512   // 4*H

// 256 MB scratch for precomputed input gates: pre[t][b][512] = x@W_ih^T + b
__device__ float g_pre[(size_t)SS * BB * GG];

typedef unsigned long long ull;

// Packed fp32x2 ops (sm_100+)
#define FMA_F32X2(d, a, b, c) \
    asm("fma.rn.f32x2 %0, %1, %2, %3;" : "=l"(d) : "l"(a), "l"(b), "l"(c))
#define ADD_F32X2(d, a, b) \
    asm("add.rn.f32x2 %0, %1, %2;" : "=l"(d) : "l"(a), "l"(b))
#define PACK_DUP(out, f) \
    asm("mov.b64 %0, {%1, %1};" : "=l"(out) : "r"(__float_as_uint(f)))
#define UNPACK2(lo, hi, in) \
    asm("mov.b64 {%0, %1}, %2;" : "=f"(lo), "=f"(hi) : "l"(in))
// Single-instruction tanh (MUFU.TANH, sm_75+)
#define TANH_APPROX(d, x) \
    asm("tanh.approx.f32 %0, %1;" : "=f"(d) : "f"(x))

// ---------------------------------------------------------------------------
// Kernel P: pre = X @ W_ih^T + bias (f32x2 version, passing since R3)
// ---------------------------------------------------------------------------
#define PSTRIDE 132
__global__ void __launch_bounds__(256) pre_gemm_kernel(
    const float* __restrict__ X,
    const float* __restrict__ Wih,
    const float* __restrict__ bias)
{
    extern __shared__ float sm[];
    float* Xs = sm;                       // [128][PSTRIDE]
    float* Ws = sm + 128 * PSTRIDE;       // [128][PSTRIDE]

    const int tid = threadIdx.x;
    const int row0 = blockIdx.x * 128;
    const int col0 = blockIdx.y * 128;

    #pragma unroll
    for (int it = 0; it < 64; it++) {
        int idx = it * 256 + tid;
        int i = idx >> 7;
        int k = idx & 127;
        Xs[k * PSTRIDE + i] = X[(size_t)(row0 + i) * DD + k];
    }
    #pragma unroll
    for (int it = 0; it < 64; it++) {
        int idx = it * 256 + tid;
        int j = idx >> 7;
        int k = idx & 127;
        Ws[k * PSTRIDE + j] = Wih[(size_t)(col0 + j) * DD + k];
    }
    __syncthreads();

    const int tx = tid & 15;
    const int ty = tid >> 4;

    ull acc2[8][4];
    #pragma unroll
    for (int i = 0; i < 8; i++)
        #pragma unroll
        for (int j = 0; j < 4; j++) acc2[i][j] = 0ULL;

    #pragma unroll 4
    for (int k = 0; k < 128; k++) {
        float4 a0 = *(const float4*)&Xs[k * PSTRIDE + ty * 8];
        float4 a1 = *(const float4*)&Xs[k * PSTRIDE + ty * 8 + 4];
        ulonglong2 b0 = *(const ulonglong2*)&Ws[k * PSTRIDE + tx * 8];
        ulonglong2 b1 = *(const ulonglong2*)&Ws[k * PSTRIDE + tx * 8 + 4];
        float av[8] = {a0.x, a0.y, a0.z, a0.w, a1.x, a1.y, a1.z, a1.w};
        ull bp[4] = {b0.x, b0.y, b1.x, b1.y};
        #pragma unroll
        for (int i = 0; i < 8; i++) {
            ull aa;
            PACK_DUP(aa, av[i]);
            #pragma unroll
            for (int j = 0; j < 4; j++)
                FMA_F32X2(acc2[i][j], aa, bp[j], acc2[i][j]);
        }
    }

    const int gcol = col0 + tx * 8;
    float bv8[8];
    #pragma unroll
    for (int j = 0; j < 8; j++) bv8[j] = bias[gcol + j];

    #pragma unroll
    for (int i = 0; i < 8; i++) {
        size_t r = (size_t)(row0 + ty * 8 + i);
        float* dst = g_pre + r * GG + gcol;
        float res[8];
        #pragma unroll
        for (int j = 0; j < 4; j++) {
            float lo, hi;
            UNPACK2(lo, hi, acc2[i][j]);
            res[2 * j]     = lo + bv8[2 * j];
            res[2 * j + 1] = hi + bv8[2 * j + 1];
        }
        *(float4*)&dst[0] = make_float4(res[0], res[1], res[2], res[3]);
        *(float4*)&dst[4] = make_float4(res[4], res[5], res[6], res[7]);
    }
}

// ---------------------------------------------------------------------------
// Cluster helpers
// ---------------------------------------------------------------------------
__device__ __forceinline__ uint32_t smem_u32(const void* p) {
    uint32_t a;
    asm("{ .reg .u64 t; cvta.to.shared.u64 t, %1; cvt.u32.u64 %0, t; }"
        : "=r"(a) : "l"(p));
    return a;
}
__device__ __forceinline__ uint32_t my_ctarank() {
    uint32_t r;
    asm("mov.u32 %0, %%cluster_ctarank;" : "=r"(r));
    return r;
}
__device__ __forceinline__ uint32_t mapa_u32(uint32_t local, uint32_t rank) {
    uint32_t r;
    asm("mapa.shared::cluster.u32 %0, %1, %2;" : "=r"(r) : "r"(local), "r"(rank));
    return r;
}
__device__ __forceinline__ void mbar_init(uint32_t addr, uint32_t count) {
    asm volatile("mbarrier.init.shared.b64 [%0], %1;"
                 :: "r"(addr), "r"(count) : "memory");
}
// Async store with HW transaction tracking (data + signal, no fences).
__device__ __forceinline__ void st_async_f32(uint32_t dst, float v, uint32_t mbar) {
    asm volatile(
        "st.async.shared::cluster.mbarrier::complete_tx::bytes.b32 [%0], %1, [%2];"
        :: "r"(dst), "r"(__float_as_uint(v)), "r"(mbar) : "memory");
}
__device__ __forceinline__ void mbar_expect_tx(uint32_t mbar, uint32_t bytes) {
    asm volatile("mbarrier.arrive.expect_tx.shared.b64 _, [%0], %1;"
                 :: "r"(mbar), "r"(bytes) : "memory");
}
__device__ __forceinline__ void mbar_wait(uint32_t mbar, uint32_t parity) {
    asm volatile(
        "{\n\t"
        ".reg .pred P;\n"
        "WL_%=:\n\t"
        "mbarrier.try_wait.parity.acquire.cta.shared::cta.b64 P, [%0], %1, 0x989680;\n\t"
        "@P bra WD_%=;\n\t"
        "bra WL_%=;\n"
        "WD_%=:\n\t"
        "}"
        :: "r"(mbar), "r"(parity) : "memory");
}
__device__ __forceinline__ void cluster_sync_hw() {
    asm volatile("barrier.cluster.arrive.aligned;" ::: "memory");
    asm volatile("barrier.cluster.wait.aligned;" ::: "memory");
}

// ---------------------------------------------------------------------------
// Kernel R: reverse scan, one 2-CTA CLUSTER per batch element (R6 winner).
// rank0 owns gate rows 0:256 (i,f); rank1 owns 256:512 (g,o). 256 thr/CTA,
// ALL 128 W_hh weights per thread register-resident.
// R8 deltas vs R6: tanh.approx activations (1 MUFU instead of exp/div
// chains, twice on the critical path) + depth-2 pre/tv prefetch.
// ---------------------------------------------------------------------------
__global__ void __launch_bounds__(256, 1) __cluster_dims__(2, 1, 1)
lstm_rev_cluster_kernel(
    const float* __restrict__ timeArr,   // [S*B]
    const float* __restrict__ Whh,       // [512,128]
    const float* __restrict__ w_t,       // [128]
    const float* __restrict__ b_t,       // [128]
    float* __restrict__ out)             // outputs ++ h ++ c
{
    __shared__ __align__(16) float hbuf[2][128];
    __shared__ float act_all[2][512];
    __shared__ ull   mbars[2];

    const int tid   = threadIdx.x;
    const uint32_t rank  = my_ctarank();
    const uint32_t prank = 1u - rank;
    const int batch = blockIdx.x >> 1;
    const int grow  = (int)rank * 256 + tid;   // global gate row

    // ALL weights register-resident: 64 ull = 128 floats
    ull wR[64];
    {
        const ull* wp = (const ull*)(Whh + (size_t)grow * HH);
        #pragma unroll
        for (int c = 0; c < 64; c++) wR[c] = wp[c];
    }

    // Cluster-space addresses: my act slot in BOTH CTAs + both CTAs' mbars
    const uint32_t mb0_l = smem_u32(&mbars[0]);
    const uint32_t mb1_l = smem_u32(&mbars[1]);
    uint32_t dst_own[2], dst_peer[2], mb_own[2], mb_peer[2];
    #pragma unroll
    for (int m = 0; m < 2; m++) {
        uint32_t a = smem_u32(&act_all[m][grow]);
        dst_own[m]  = mapa_u32(a, rank);
        dst_peer[m] = mapa_u32(a, prank);
        uint32_t mb = (m == 0) ? mb0_l : mb1_l;
        mb_own[m]   = mapa_u32(mb, rank);
        mb_peer[m]  = mapa_u32(mb, prank);
    }

    if (tid == 0) {
        mbar_init(mb0_l, 1);
        mbar_init(mb1_l, 1);
        // pre-arm both barriers for steps 0 and 1 (512 floats = 2048 B each)
        mbar_expect_tx(mb0_l, 2048);
        mbar_expect_tx(mb1_l, 2048);
    }
    if (tid < 128) hbuf[0][tid] = 0.0f;

    const float wt = w_t[tid & 127];
    const float bt = b_t[tid & 127];
    float creg = 0.0f, hlast = 0.0f;

    __syncthreads();
    cluster_sync_hw();   // mbars init+armed visible cluster-wide

    const float* preP = g_pre + (size_t)batch * GG + grow;

    // depth-2 prefetch pipeline for pre/tv
    float pre_n1 = preP[(size_t)(SS - 1) * BB * GG];
    float tv_n1  = timeArr[(size_t)(SS - 1) * BB + batch];
    float pre_n2 = (SS >= 2) ? preP[(size_t)(SS - 2) * BB * GG] : 0.0f;
    float tv_n2  = (SS >= 2) ? timeArr[(size_t)(SS - 2) * BB + batch] : 0.0f;

    const bool  is_g     = (rank == 1) && (tid < 128);
    // tanh path: g-gate uses tanh(x) directly; sigmoid = 0.5*tanh(x/2)+0.5
    const float pre_mul  = is_g ? 1.0f : 0.5f;

    for (int s = 0; s < SS; s++) {
        const int t   = SS - 1 - s;
        const int cur = s & 1;
        const int m   = s & 1;
        const uint32_t par = (uint32_t)((s >> 1) & 1);

        const float pre_j = pre_n1;
        const float tv    = tv_n1;
        pre_n1 = pre_n2;
        tv_n1  = tv_n2;
        if (t >= 2) {   // prefetch two steps ahead
            pre_n2 = preP[(size_t)(t - 2) * BB * GG];
            tv_n2  = timeArr[(size_t)(t - 2) * BB + batch];
        }

        // dot: gates[grow] = pre + W_hh[grow].h  (weights in regs,
        // 8 independent accumulator chains)
        const ulonglong2* h2 = (const ulonglong2*)&hbuf[cur][0];
        ull ac[8];
        #pragma unroll
        for (int i = 0; i < 8; i++) ac[i] = 0ULL;
        #pragma unroll
        for (int i = 0; i < 8; i++) {
            ulonglong2 hva = h2[4 * i],     hvb = h2[4 * i + 1];
            ulonglong2 hvc = h2[4 * i + 2], hvd = h2[4 * i + 3];
            FMA_F32X2(ac[0], wR[8 * i],     hva.x, ac[0]);
            FMA_F32X2(ac[1], wR[8 * i + 1], hva.y, ac[1]);
            FMA_F32X2(ac[2], wR[8 * i + 2], hvb.x, ac[2]);
            FMA_F32X2(ac[3], wR[8 * i + 3], hvb.y, ac[3]);
            FMA_F32X2(ac[4], wR[8 * i + 4], hvc.x, ac[4]);
            FMA_F32X2(ac[5], wR[8 * i + 5], hvc.y, ac[5]);
            FMA_F32X2(ac[6], wR[8 * i + 6], hvd.x, ac[6]);
            FMA_F32X2(ac[7], wR[8 * i + 7], hvd.y, ac[7]);
        }
        ADD_F32X2(ac[0], ac[0], ac[1]);
        ADD_F32X2(ac[2], ac[2], ac[3]);
        ADD_F32X2(ac[4], ac[4], ac[5]);
        ADD_F32X2(ac[6], ac[6], ac[7]);
        ADD_F32X2(ac[0], ac[0], ac[2]);
        ADD_F32X2(ac[4], ac[4], ac[6]);
        ADD_F32X2(ac[0], ac[0], ac[4]);
        float lo, hi;
        UNPACK2(lo, hi, ac[0]);
        float gsum = pre_j + (lo + hi);

        // activation via single MUFU.TANH:
        //   g-gate: tanh(gsum);  others: sigmoid = 0.5*tanh(0.5*gsum)+0.5
        float th;
        TANH_APPROX(th, pre_mul * gsum);
        float a = is_g ? th : fmaf(0.5f, th, 0.5f);

        // publish act to BOTH CTAs via async stores (HW tx tracking)
        st_async_f32(dst_own[m],  a, mb_own[m]);
        st_async_f32(dst_peer[m], a, mb_peer[m]);

        // single wait covers local + remote acts
        mbar_wait(m ? mb1_l : mb0_l, par);
        if (tid == 0)  // re-arm this barrier for step s+2 (ordered by the
            mbar_expect_tx(m ? mb1_l : mb0_l, 2048);  // __syncthreads below)

        if (tid < 128) {
            const float* A = &act_all[m][0];
            float iv = A[tid];
            float fv = A[128 + tid];
            float gv = A[256 + tid];
            float ov = A[384 + tid];
            float dec = __expf(-fmaxf(tv * wt + bt, 0.0f));
            creg = fv * creg * dec + iv * gv;
            float tc;
            TANH_APPROX(tc, creg);
            float hv = ov * tc;
            hlast = hv;
            hbuf[cur ^ 1][tid] = hv;
            out[(size_t)t * (BB * HH) + (size_t)batch * HH + tid] = hv;
        }
        __syncthreads();   // h published; also orders re-arm before s+1 sends
    }

    // final state: h then c after the outputs block (rank0 only; rank1's
    // redundant out[] writes above are bit-identical so either may win)
    if (rank == 0 && tid < 128) {
        size_t base = (size_t)SS * BB * HH;
        out[base + (size_t)batch * HH + tid] = hlast;
        out[base + (size_t)BB * HH + (size_t)batch * HH + tid] = creg;
    }

    cluster_sync_hw();   // no early exit while peer ops in flight
}

// ---------------------------------------------------------------------------
// Launch
// ---------------------------------------------------------------------------
extern "C" void kernel_launch(void* const* d_in, const int* in_sizes, int n_in,
                              void* d_out, int out_size)
{
    const float* X    = (const float*)d_in[0];  // input  (S,B,D)
    const float* Tm   = (const float*)d_in[1];  // time   (S,B,1)
    const float* Wih  = (const float*)d_in[2];  // (4H, D)
    const float* Whh  = (const float*)d_in[3];  // (4H, H)
    const float* bias = (const float*)d_in[4];  // (4H,)
    const float* wt   = (const float*)d_in[5];  // (H,)
    const float* bt   = (const float*)d_in[6];  // (H,)
    float* out = (float*)d_out;

    const int smemP = 2 * 128 * PSTRIDE * (int)sizeof(float);  // 135168 B
    cudaFuncSetAttribute(pre_gemm_kernel,
                         cudaFuncAttributeMaxDynamicSharedMemorySize, smemP);

    dim3 gridP((SS * BB) / 128, GG / 128);
    pre_gemm_kernel<<<gridP, 256, smemP>>>(X, Wih, bias);

    // 64 clusters of 2 CTAs (grid 128), 256 threads each
    lstm_rev_cluster_kernel<<<BB * 2, 256>>>(Tm, Whh, wt, bt, out);
}

// round 10
// speedup vs baseline: 1.6347x; 1.0424x over previous
#include <cuda_runtime.h>
#include <cuda_bf16.h>
#include <cstddef>
#include <cstdint>

// Problem constants
#define SS 2048
#define BB 64
#define DD 128
#define HH 128
#define GG 512   // 4*H

// 256 MB scratch for precomputed input gates: pre[t][b][512] = x@W_ih^T + b
__device__ float g_pre[(size_t)SS * BB * GG];

typedef unsigned long long ull;

// Packed fp32x2 ops (sm_100+)
#define FMA_F32X2(d, a, b, c) \
    asm("fma.rn.f32x2 %0, %1, %2, %3;" : "=l"(d) : "l"(a), "l"(b), "l"(c))
#define ADD_F32X2(d, a, b) \
    asm("add.rn.f32x2 %0, %1, %2;" : "=l"(d) : "l"(a), "l"(b))
#define PACK_DUP(out, f) \
    asm("mov.b64 %0, {%1, %1};" : "=l"(out) : "r"(__float_as_uint(f)))
#define UNPACK2(lo, hi, in) \
    asm("mov.b64 {%0, %1}, %2;" : "=f"(lo), "=f"(hi) : "l"(in))
// Single-instruction tanh (MUFU.TANH, sm_75+)
#define TANH_APPROX(d, x) \
    asm("tanh.approx.f32 %0, %1;" : "=f"(d) : "f"(x))

// ---------------------------------------------------------------------------
// Kernel P: pre = X @ W_ih^T + bias (f32x2 version, passing since R3)
// ---------------------------------------------------------------------------
#define PSTRIDE 132
__global__ void __launch_bounds__(256) pre_gemm_kernel(
    const float* __restrict__ X,
    const float* __restrict__ Wih,
    const float* __restrict__ bias)
{
    extern __shared__ float sm[];
    float* Xs = sm;                       // [128][PSTRIDE]
    float* Ws = sm + 128 * PSTRIDE;       // [128][PSTRIDE]

    const int tid = threadIdx.x;
    const int row0 = blockIdx.x * 128;
    const int col0 = blockIdx.y * 128;

    #pragma unroll
    for (int it = 0; it < 64; it++) {
        int idx = it * 256 + tid;
        int i = idx >> 7;
        int k = idx & 127;
        Xs[k * PSTRIDE + i] = X[(size_t)(row0 + i) * DD + k];
    }
    #pragma unroll
    for (int it = 0; it < 64; it++) {
        int idx = it * 256 + tid;
        int j = idx >> 7;
        int k = idx & 127;
        Ws[k * PSTRIDE + j] = Wih[(size_t)(col0 + j) * DD + k];
    }
    __syncthreads();

    const int tx = tid & 15;
    const int ty = tid >> 4;

    ull acc2[8][4];
    #pragma unroll
    for (int i = 0; i < 8; i++)
        #pragma unroll
        for (int j = 0; j < 4; j++) acc2[i][j] = 0ULL;

    #pragma unroll 4
    for (int k = 0; k < 128; k++) {
        float4 a0 = *(const float4*)&Xs[k * PSTRIDE + ty * 8];
        float4 a1 = *(const float4*)&Xs[k * PSTRIDE + ty * 8 + 4];
        ulonglong2 b0 = *(const ulonglong2*)&Ws[k * PSTRIDE + tx * 8];
        ulonglong2 b1 = *(const ulonglong2*)&Ws[k * PSTRIDE + tx * 8 + 4];
        float av[8] = {a0.x, a0.y, a0.z, a0.w, a1.x, a1.y, a1.z, a1.w};
        ull bp[4] = {b0.x, b0.y, b1.x, b1.y};
        #pragma unroll
        for (int i = 0; i < 8; i++) {
            ull aa;
            PACK_DUP(aa, av[i]);
            #pragma unroll
            for (int j = 0; j < 4; j++)
                FMA_F32X2(acc2[i][j], aa, bp[j], acc2[i][j]);
        }
    }

    const int gcol = col0 + tx * 8;
    float bv8[8];
    #pragma unroll
    for (int j = 0; j < 8; j++) bv8[j] = bias[gcol + j];

    #pragma unroll
    for (int i = 0; i < 8; i++) {
        size_t r = (size_t)(row0 + ty * 8 + i);
        float* dst = g_pre + r * GG + gcol;
        float res[8];
        #pragma unroll
        for (int j = 0; j < 4; j++) {
            float lo, hi;
            UNPACK2(lo, hi, acc2[i][j]);
            res[2 * j]     = lo + bv8[2 * j];
            res[2 * j + 1] = hi + bv8[2 * j + 1];
        }
        *(float4*)&dst[0] = make_float4(res[0], res[1], res[2], res[3]);
        *(float4*)&dst[4] = make_float4(res[4], res[5], res[6], res[7]);
    }
}

// ---------------------------------------------------------------------------
// Cluster helpers
// ---------------------------------------------------------------------------
__device__ __forceinline__ uint32_t smem_u32(const void* p) {
    uint32_t a;
    asm("{ .reg .u64 t; cvta.to.shared.u64 t, %1; cvt.u32.u64 %0, t; }"
        : "=r"(a) : "l"(p));
    return a;
}
__device__ __forceinline__ uint32_t my_ctarank() {
    uint32_t r;
    asm("mov.u32 %0, %%cluster_ctarank;" : "=r"(r));
    return r;
}
__device__ __forceinline__ uint32_t mapa_u32(uint32_t local, uint32_t rank) {
    uint32_t r;
    asm("mapa.shared::cluster.u32 %0, %1, %2;" : "=r"(r) : "r"(local), "r"(rank));
    return r;
}
__device__ __forceinline__ void mbar_init(uint32_t addr, uint32_t count) {
    asm volatile("mbarrier.init.shared.b64 [%0], %1;"
                 :: "r"(addr), "r"(count) : "memory");
}
// Async store with HW transaction tracking (data + signal, no fences).
__device__ __forceinline__ void st_async_f32(uint32_t dst, float v, uint32_t mbar) {
    asm volatile(
        "st.async.shared::cluster.mbarrier::complete_tx::bytes.b32 [%0], %1, [%2];"
        :: "r"(dst), "r"(__float_as_uint(v)), "r"(mbar) : "memory");
}
__device__ __forceinline__ void mbar_expect_tx(uint32_t mbar, uint32_t bytes) {
    asm volatile("mbarrier.arrive.expect_tx.shared.b64 _, [%0], %1;"
                 :: "r"(mbar), "r"(bytes) : "memory");
}
__device__ __forceinline__ void mbar_wait(uint32_t mbar, uint32_t parity) {
    asm volatile(
        "{\n\t"
        ".reg .pred P;\n"
        "WL_%=:\n\t"
        "mbarrier.try_wait.parity.acquire.cta.shared::cta.b64 P, [%0], %1, 0x989680;\n\t"
        "@P bra WD_%=;\n\t"
        "bra WL_%=;\n"
        "WD_%=:\n\t"
        "}"
        :: "r"(mbar), "r"(parity) : "memory");
}
__device__ __forceinline__ void cluster_sync_hw() {
    asm volatile("barrier.cluster.arrive.aligned;" ::: "memory");
    asm volatile("barrier.cluster.wait.aligned;" ::: "memory");
}

// ---------------------------------------------------------------------------
// Kernel R: reverse scan, one 2-CTA CLUSTER per batch element.
// rank0 owns gate rows 0:256 (i,f); rank1 owns 256:512 (g,o). 256 thr/CTA,
// ALL 128 W_hh weights per thread register-resident.
// R9/R10 deltas vs R8 (R9 bench was an infra failure; identical resubmit):
//  - decay exp + creg*dec hoisted BEFORE the wait (off the serial tail)
//  - local acts via plain STS (st.async only to PEER; mbar expects 1024 B);
//    a __syncthreads before the wait publishes local acts while the peer
//    DSMEM flight (~215 cyc) is in the air.
// ---------------------------------------------------------------------------
__global__ void __launch_bounds__(256, 1) __cluster_dims__(2, 1, 1)
lstm_rev_cluster_kernel(
    const float* __restrict__ timeArr,   // [S*B]
    const float* __restrict__ Whh,       // [512,128]
    const float* __restrict__ w_t,       // [128]
    const float* __restrict__ b_t,       // [128]
    float* __restrict__ out)             // outputs ++ h ++ c
{
    __shared__ __align__(16) float hbuf[2][128];
    __shared__ float act_all[2][512];
    __shared__ ull   mbars[2];

    const int tid   = threadIdx.x;
    const uint32_t rank  = my_ctarank();
    const uint32_t prank = 1u - rank;
    const int batch = blockIdx.x >> 1;
    const int grow  = (int)rank * 256 + tid;   // global gate row

    // ALL weights register-resident: 64 ull = 128 floats
    ull wR[64];
    {
        const ull* wp = (const ull*)(Whh + (size_t)grow * HH);
        #pragma unroll
        for (int c = 0; c < 64; c++) wR[c] = wp[c];
    }

    // Cluster-space addresses: my act slot in the PEER CTA + peer's mbars
    const uint32_t mb0_l = smem_u32(&mbars[0]);
    const uint32_t mb1_l = smem_u32(&mbars[1]);
    uint32_t dst_peer[2], mb_peer[2];
    #pragma unroll
    for (int m = 0; m < 2; m++) {
        uint32_t a = smem_u32(&act_all[m][grow]);
        dst_peer[m] = mapa_u32(a, prank);
        uint32_t mb = (m == 0) ? mb0_l : mb1_l;
        mb_peer[m]  = mapa_u32(mb, prank);
    }

    if (tid == 0) {
        mbar_init(mb0_l, 1);
        mbar_init(mb1_l, 1);
        // pre-arm both barriers for steps 0 and 1 (peer's 256 floats each)
        mbar_expect_tx(mb0_l, 1024);
        mbar_expect_tx(mb1_l, 1024);
    }
    if (tid < 128) hbuf[0][tid] = 0.0f;

    const float wt = w_t[tid & 127];
    const float bt = b_t[tid & 127];
    float creg = 0.0f, hlast = 0.0f;

    __syncthreads();
    cluster_sync_hw();   // mbars init+armed visible cluster-wide

    const float* preP = g_pre + (size_t)batch * GG + grow;

    // depth-2 prefetch pipeline for pre/tv
    float pre_n1 = preP[(size_t)(SS - 1) * BB * GG];
    float tv_n1  = timeArr[(size_t)(SS - 1) * BB + batch];
    float pre_n2 = preP[(size_t)(SS - 2) * BB * GG];
    float tv_n2  = timeArr[(size_t)(SS - 2) * BB + batch];

    const bool  is_g     = (rank == 1) && (tid < 128);
    // tanh path: g-gate uses tanh(x) directly; sigmoid = 0.5*tanh(x/2)+0.5
    const float pre_mul  = is_g ? 1.0f : 0.5f;

    for (int s = 0; s < SS; s++) {
        const int t   = SS - 1 - s;
        const int cur = s & 1;
        const int m   = s & 1;
        const uint32_t par = (uint32_t)((s >> 1) & 1);

        const float pre_j = pre_n1;
        const float tv    = tv_n1;
        pre_n1 = pre_n2;
        tv_n1  = tv_n2;
        if (t >= 2) {   // prefetch two steps ahead
            pre_n2 = preP[(size_t)(t - 2) * BB * GG];
            tv_n2  = timeArr[(size_t)(t - 2) * BB + batch];
        }

        // dot: gates[grow] = pre + W_hh[grow].h  (weights in regs,
        // 8 independent accumulator chains)
        const ulonglong2* h2 = (const ulonglong2*)&hbuf[cur][0];
        ull ac[8];
        #pragma unroll
        for (int i = 0; i < 8; i++) ac[i] = 0ULL;
        #pragma unroll
        for (int i = 0; i < 8; i++) {
            ulonglong2 hva = h2[4 * i],     hvb = h2[4 * i + 1];
            ulonglong2 hvc = h2[4 * i + 2], hvd = h2[4 * i + 3];
            FMA_F32X2(ac[0], wR[8 * i],     hva.x, ac[0]);
            FMA_F32X2(ac[1], wR[8 * i + 1], hva.y, ac[1]);
            FMA_F32X2(ac[2], wR[8 * i + 2], hvb.x, ac[2]);
            FMA_F32X2(ac[3], wR[8 * i + 3], hvb.y, ac[3]);
            FMA_F32X2(ac[4], wR[8 * i + 4], hvc.x, ac[4]);
            FMA_F32X2(ac[5], wR[8 * i + 5], hvc.y, ac[5]);
            FMA_F32X2(ac[6], wR[8 * i + 6], hvd.x, ac[6]);
            FMA_F32X2(ac[7], wR[8 * i + 7], hvd.y, ac[7]);
        }
        ADD_F32X2(ac[0], ac[0], ac[1]);
        ADD_F32X2(ac[2], ac[2], ac[3]);
        ADD_F32X2(ac[4], ac[4], ac[5]);
        ADD_F32X2(ac[6], ac[6], ac[7]);
        ADD_F32X2(ac[0], ac[0], ac[2]);
        ADD_F32X2(ac[4], ac[4], ac[6]);
        ADD_F32X2(ac[0], ac[0], ac[4]);
        float lo, hi;
        UNPACK2(lo, hi, ac[0]);
        float gsum = pre_j + (lo + hi);

        // activation via single MUFU.TANH:
        //   g-gate: tanh(gsum);  others: sigmoid = 0.5*tanh(0.5*gsum)+0.5
        float th;
        TANH_APPROX(th, pre_mul * gsum);
        float a = is_g ? th : fmaf(0.5f, th, 0.5f);

        // publish act: plain STS locally, st.async to PEER only
        act_all[m][grow] = a;
        st_async_f32(dst_peer[m], a, mb_peer[m]);

        // decay term hoisted off the post-wait critical path: depends only
        // on tv/wt/bt/creg, all available now.
        float cfd = 0.0f;
        if (tid < 128) {
            float dec = __expf(-fmaxf(tv * wt + bt, 0.0f));
            cfd = creg * dec;
        }

        __syncthreads();                    // local acts visible (overlaps
                                            // the peer DSMEM flight)
        mbar_wait(m ? mb1_l : mb0_l, par);  // peer acts visible
        if (tid == 0)  // re-arm this barrier for step s+2 (ordered before
            mbar_expect_tx(m ? mb1_l : mb0_l, 1024);  // s+1 sends by the
                                                      // end-of-step bar)
        if (tid < 128) {
            const float* A = &act_all[m][0];
            float iv = A[tid];
            float fv = A[128 + tid];
            float gv = A[256 + tid];
            float ov = A[384 + tid];
            creg = fv * cfd + iv * gv;      // dec already folded into cfd
            float tc;
            TANH_APPROX(tc, creg);
            float hv = ov * tc;
            hlast = hv;
            hbuf[cur ^ 1][tid] = hv;
            out[(size_t)t * (BB * HH) + (size_t)batch * HH + tid] = hv;
        }
        __syncthreads();   // h published; also orders re-arm before s+1 sends
    }

    // final state: h then c after the outputs block (rank0 only; rank1's
    // redundant out[] writes above are bit-identical so either may win)
    if (rank == 0 && tid < 128) {
        size_t base = (size_t)SS * BB * HH;
        out[base + (size_t)batch * HH + tid] = hlast;
        out[base + (size_t)BB * HH + (size_t)batch * HH + tid] = creg;
    }

    cluster_sync_hw();   // no early exit while peer ops in flight
}

// ---------------------------------------------------------------------------
// Launch
// ---------------------------------------------------------------------------
extern "C" void kernel_launch(void* const* d_in, const int* in_sizes, int n_in,
                              void* d_out, int out_size)
{
    const float* X    = (const float*)d_in[0];  // input  (S,B,D)
    const float* Tm   = (const float*)d_in[1];  // time   (S,B,1)
    const float* Wih  = (const float*)d_in[2];  // (4H, D)
    const float* Whh  = (const float*)d_in[3];  // (4H, H)
    const float* bias = (const float*)d_in[4];  // (4H,)
    const float* wt   = (const float*)d_in[5];  // (H,)
    const float* bt   = (const float*)d_in[6];  // (H,)
    float* out = (float*)d_out;

    const int smemP = 2 * 128 * PSTRIDE * (int)sizeof(float);  // 135168 B
    cudaFuncSetAttribute(pre_gemm_kernel,
                         cudaFuncAttributeMaxDynamicSharedMemorySize, smemP);

    dim3 gridP((SS * BB) / 128, GG / 128);
    pre_gemm_kernel<<<gridP, 256, smemP>>>(X, Wih, bias);

    // 64 clusters of 2 CTAs (grid 128), 256 threads each
    lstm_rev_cluster_kernel<<<BB * 2, 256>>>(Tm, Whh, wt, bt, out);
}